// round 8
// baseline (speedup 1.0000x reference)
#include <cuda_runtime.h>
#include <math.h>

#define NB   256            // graphs
#define NRr  268            // ROIs per graph
#define NT   (NB*NRr)       // total nodes = 68608
#define IC   256
#define OC   64
#define NCm  7
#define DEG  32
#define EPG  (NRr*DEG)      // edges per graph = 8576
#define ET   (NT*DEG)       // total edges = 2195456
#define KK   214            // top-k per graph
#define QT   256            // sigmoid table resolution
#define LN_EPS 1e-5f
#define CHUNK (EPG/8)       // 1072 edges per warp in k_csr

// output layout (float32, concatenated in reference return order)
#define XP_OFF   0
#define BAT_OFF  (NB*KK*OC)                 // 3506176
#define SC_OFF   (BAT_OFF + NB*KK)          // 3560960
#define PERM_OFF (SC_OFF + NT)              // 3629568

// ---------------- scratch (device globals; no allocation allowed) ----------
__device__ float g_tab[(QT+1)*OC];          // sigmoid(ea*w[c]+b[c]) table, row QT = self-loop gate
__device__ float g_xt[NT*OC];               // xt (per-node transform result)
__device__ float g_out[NT*OC];              // h after fused conv+ELU+LN
__device__ int   g_bsrc[ET];                // CSR bucket: global src node per slot
__device__ float g_bea[ET];                 // CSR bucket: edge_attr per slot
__device__ int   g_off[NT+1];               // CSR offsets (global edge space)

// ---------------- kernels --------------------------------------------------
__global__ void k_tab(const float* __restrict__ w, const float* __restrict__ b) {
    int q = blockIdx.x, c = threadIdx.x;
    double x = ((double)q / (double)QT) * (double)w[c] + (double)b[c];
    g_tab[q*OC + c] = (float)(1.0 / (1.0 + exp(-x)));
}

// Fused ROI-kernel mix + grouped GEMM.
// Block (r, half): ROI r, 128 graphs. Thread: gb = tid>>3 (32 graph slots),
// go = tid&7 (8 output channels). Each thread: 4 graphs x 8 outputs.
// Per k-step: 2 LDS.128 + 32 FMA (16:1 ratio) => fma-pipe bound.
__global__ void __launch_bounds__(256) k_xt(const float* __restrict__ x,
                                            const float* __restrict__ basis,
                                            const float* __restrict__ rc) {
    __shared__ float Ws[64*OC];             // 16 KB k-tile of mixed W
    __shared__ float cws[NCm];
    int r = blockIdx.x, half = blockIdx.y;
    int tid = threadIdx.x;
    int gb = tid >> 3, go = tid & 7;

    if (tid == 0) {
        double v[NCm]; double m = -1e300;
        #pragma unroll
        for (int c = 0; c < NCm; c++) { v[c] = (double)rc[r*NCm + c]; if (v[c] > m) m = v[c]; }
        double s = 0.0;
        #pragma unroll
        for (int c = 0; c < NCm; c++) { v[c] = exp(v[c] - m); s += v[c]; }
        #pragma unroll
        for (int c = 0; c < NCm; c++) cws[c] = (float)(v[c] / s);
    }
    __syncthreads();
    float cwv[NCm];
    #pragma unroll
    for (int c = 0; c < NCm; c++) cwv[c] = cws[c];

    const float4* xr4[4];
    #pragma unroll
    for (int j = 0; j < 4; j++) {
        int g = half*128 + gb + 32*j;
        xr4[j] = (const float4*)(x + ((size_t)(g*NRr + r))*IC);
    }
    float4 a0[4], a1[4];
    #pragma unroll
    for (int j = 0; j < 4; j++) {
        a0[j] = make_float4(0.f,0.f,0.f,0.f);
        a1[j] = make_float4(0.f,0.f,0.f,0.f);
    }
    const float4* b4 = (const float4*)basis;
    float4* Ws4 = (float4*)Ws;

    for (int kt = 0; kt < 4; kt++) {
        __syncthreads();
        // stage mixed W k-tile: Ws[kk][o] = sum_c cw[c]*basis[c][kt*64+kk][o]
        for (int i = tid; i < 64*OC/4; i += 256) {
            float4 acc = make_float4(0.f,0.f,0.f,0.f);
            #pragma unroll
            for (int c = 0; c < NCm; c++) {
                float4 t = b4[c*(IC*OC/4) + kt*(64*OC/4) + i];
                acc.x += cwv[c]*t.x; acc.y += cwv[c]*t.y;
                acc.z += cwv[c]*t.z; acc.w += cwv[c]*t.w;
            }
            Ws4[i] = acc;
        }
        __syncthreads();
        for (int k4 = 0; k4 < 16; k4++) {
            float4 xv0 = xr4[0][kt*16 + k4];
            float4 xv1 = xr4[1][kt*16 + k4];
            float4 xv2 = xr4[2][kt*16 + k4];
            float4 xv3 = xr4[3][kt*16 + k4];
            #pragma unroll
            for (int kk = 0; kk < 4; kk++) {
                const float4* wrow = (const float4*)(Ws + (k4*4 + kk)*OC + go*8);
                float4 w0 = wrow[0], w1 = wrow[1];
                float xs;
                xs = (&xv0.x)[kk];
                a0[0].x += xs*w0.x; a0[0].y += xs*w0.y; a0[0].z += xs*w0.z; a0[0].w += xs*w0.w;
                a1[0].x += xs*w1.x; a1[0].y += xs*w1.y; a1[0].z += xs*w1.z; a1[0].w += xs*w1.w;
                xs = (&xv1.x)[kk];
                a0[1].x += xs*w0.x; a0[1].y += xs*w0.y; a0[1].z += xs*w0.z; a0[1].w += xs*w0.w;
                a1[1].x += xs*w1.x; a1[1].y += xs*w1.y; a1[1].z += xs*w1.z; a1[1].w += xs*w1.w;
                xs = (&xv2.x)[kk];
                a0[2].x += xs*w0.x; a0[2].y += xs*w0.y; a0[2].z += xs*w0.z; a0[2].w += xs*w0.w;
                a1[2].x += xs*w1.x; a1[2].y += xs*w1.y; a1[2].z += xs*w1.z; a1[2].w += xs*w1.w;
                xs = (&xv3.x)[kk];
                a0[3].x += xs*w0.x; a0[3].y += xs*w0.y; a0[3].z += xs*w0.z; a0[3].w += xs*w0.w;
                a1[3].x += xs*w1.x; a1[3].y += xs*w1.y; a1[3].z += xs*w1.z; a1[3].w += xs*w1.w;
            }
        }
    }
    #pragma unroll
    for (int j = 0; j < 4; j++) {
        int g = half*128 + gb + 32*j;
        float4* outp = (float4*)(g_xt + (size_t)(g*NRr + r)*OC + go*8);
        outp[0] = a0[j]; outp[1] = a1[j];
    }
}

// Deterministic per-graph CSR build, counting-sort style, all 8 warps active.
// Bucket order = ascending edge id (stable), matching XLA scatter order.
__global__ void __launch_bounds__(256) k_csr(const int* __restrict__ ei,
                                             const float* __restrict__ eattr) {
    __shared__ unsigned short ldst[EPG];    // local dst per edge (17 KB)
    __shared__ unsigned short lpos[EPG];    // bucket slot per edge (17 KB)
    __shared__ int cw[8][NRr];              // per-warp histogram -> per-warp base (8.6 KB)
    __shared__ int tot[NRr], off[NRr];
    int g = blockIdx.x, tid = threadIdx.x;
    int lane = tid & 31, wid = tid >> 5;
    int base = g*EPG;
    int cbeg = wid*CHUNK;

    for (int i = tid; i < EPG; i += 256)
        ldst[i] = (unsigned short)(ei[ET + base + i] - g*NRr);
    for (int i = tid; i < 8*NRr; i += 256) ((int*)cw)[i] = 0;
    __syncthreads();

    for (int i = cbeg + lane; i < cbeg + CHUNK; i += 32)
        atomicAdd(&cw[wid][ldst[i]], 1);
    __syncthreads();

    for (int d = tid; d < NRr; d += 256) {
        int s = 0;
        #pragma unroll
        for (int w = 0; w < 8; w++) s += cw[w][d];
        tot[d] = s;
    }
    __syncthreads();

    if (wid == 0) {
        int carry = 0;
        for (int c = 0; c < 9; c++) {
            int idx = c*32 + lane;
            int v = (idx < NRr) ? tot[idx] : 0;
            int incl = v;
            #pragma unroll
            for (int o = 1; o < 32; o <<= 1) {
                int t = __shfl_up_sync(0xffffffffu, incl, o);
                if (lane >= o) incl += t;
            }
            if (idx < NRr) off[idx] = incl - v + carry;
            carry += __shfl_sync(0xffffffffu, incl, 31);
        }
    }
    __syncthreads();

    for (int d = tid; d < NRr; d += 256) {
        int run = off[d];
        #pragma unroll
        for (int w = 0; w < 8; w++) { int t = cw[w][d]; cw[w][d] = run; run += t; }
        g_off[g*NRr + d] = base + off[d];
    }
    if (g == NB-1 && tid == 0) g_off[NT] = ET;
    __syncthreads();

    for (int it = 0; it < (CHUNK + 31)/32; it++) {
        int idx = cbeg + it*32 + lane;
        bool valid = (idx < cbeg + CHUNK);
        int d = valid ? (int)ldst[idx] : (NRr + lane);
        unsigned mask = __match_any_sync(0xffffffffu, d);
        int rank = __popc(mask & ((1u << lane) - 1u));
        int leader = __ffs(mask) - 1;
        int prior = valid ? cw[wid][d] : 0;
        if (valid && lane == leader) cw[wid][d] = prior + __popc(mask);
        if (valid) lpos[idx] = (unsigned short)(prior + rank);
    }
    __syncthreads();

    for (int i = tid; i < EPG; i += 256) {
        int pos = base + (int)lpos[i];
        g_bsrc[pos] = ei[base + i];
        g_bea[pos]  = eattr[base + i];
    }
}

// Fused gather + self-loop + bias + ELU + LayerNorm + attention score.
// Warp per dst node, 4 nodes per warp (grid NT/32). Deterministic order.
__global__ void __launch_bounds__(256) k_gather(const float* __restrict__ cbias,
                                                const float* __restrict__ gam,
                                                const float* __restrict__ bet,
                                                const float* __restrict__ W1,
                                                const float* __restrict__ b1,
                                                const float* __restrict__ w2,
                                                const float* __restrict__ b2,
                                                float* __restrict__ dout) {
    __shared__ float W1s[OC*OC];            // 16 KB
    __shared__ float b1s[OC], w2s[OC];
    __shared__ int   s_s[8][128];
    __shared__ float s_e[8][128];
    __shared__ float hsm[8][OC];
    int tid = threadIdx.x;
    for (int i = tid; i < OC*OC; i += 256) W1s[i] = W1[i];
    if (tid < OC) { b1s[tid] = b1[tid]; w2s[tid] = w2[tid]; }
    __syncthreads();

    int w = tid >> 5, lane = tid & 31;
    float2 bb = ((const float2*)cbias)[lane];
    float2 sg = ((const float2*)(g_tab + QT*OC))[lane];
    float2 gm = ((const float2*)gam)[lane];
    float2 bt = ((const float2*)bet)[lane];
    float b1a = b1s[lane], b1b = b1s[lane+32];
    float w2a = w2s[lane], w2b = w2s[lane+32];
    float b2v = b2[0];

    for (int qn = 0; qn < 4; qn++) {
        int n = blockIdx.x*32 + w*4 + qn;
        int o0 = g_off[n];
        int cnt = g_off[n+1] - o0;
        if (cnt > 128) cnt = 128;           // statistically impossible (mean 32)
        for (int j = lane; j < cnt; j += 32) {
            s_s[w][j] = g_bsrc[o0 + j];
            s_e[w][j] = g_bea [o0 + j];
        }
        __syncwarp();
        float2 acc = make_float2(0.f, 0.f);
        #pragma unroll 4
        for (int j = 0; j < cnt; j++) {
            int s = s_s[w][j];
            float ea = s_e[w][j];
            float f = ea * (float)QT;
            int q = (int)f; if (q > QT-1) q = QT-1;
            float fr = f - (float)q;
            float2 t0 = ((const float2*)(g_tab + q*OC))[lane];
            float2 t1 = ((const float2*)(g_tab + q*OC + OC))[lane];
            float2 xv = ((const float2*)(g_xt + (size_t)s*OC))[lane];
            acc.x += xv.x * (t0.x + (t1.x - t0.x)*fr);
            acc.y += xv.y * (t0.y + (t1.y - t0.y)*fr);
        }
        // self-loop (appended last in reference), then bias
        float2 xn = ((const float2*)(g_xt + (size_t)n*OC))[lane];
        acc.x += xn.x * sg.x; acc.y += xn.y * sg.y;
        acc.x += bb.x; acc.y += bb.y;
        // ELU
        acc.x = acc.x > 0.f ? acc.x : expm1f(acc.x);
        acc.y = acc.y > 0.f ? acc.y : expm1f(acc.y);
        // LayerNorm
        float s1 = acc.x + acc.y;
        #pragma unroll
        for (int o = 16; o; o >>= 1) s1 += __shfl_xor_sync(0xffffffffu, s1, o);
        float mu = s1 * (1.f/64.f);
        float dx = acc.x - mu, dy = acc.y - mu;
        float s2 = dx*dx + dy*dy;
        #pragma unroll
        for (int o = 16; o; o >>= 1) s2 += __shfl_xor_sync(0xffffffffu, s2, o);
        float inv = 1.0f / sqrtf(s2*(1.f/64.f) + LN_EPS);
        float2 h;
        h.x = dx*inv*gm.x + bt.x;
        h.y = dy*inv*gm.y + bt.y;
        ((float2*)(g_out + (size_t)n*OC))[lane] = h;
        ((float2*)hsm[w])[lane] = h;
        __syncwarp();
        // attention score: u = tanh(h@W1+b1); sc = u@w2 + b2
        float u0 = b1a, u1 = b1b;
        #pragma unroll 8
        for (int c = 0; c < OC; c++) {
            float hc = hsm[w][c];
            u0 += hc * W1s[c*OC + lane];
            u1 += hc * W1s[c*OC + lane + 32];
        }
        float t = tanhf(u0)*w2a + tanhf(u1)*w2b;
        #pragma unroll
        for (int o = 16; o; o >>= 1) t += __shfl_xor_sync(0xffffffffu, t, o);
        if (lane == 0) dout[SC_OFF + n] = t + b2v;
        __syncwarp();
    }
}

// per-graph top-K via full bitonic sort (desc value, tie: asc index like jax top_k)
__global__ void __launch_bounds__(512) k_top(float* __restrict__ dout) {
    __shared__ float sv[512];
    __shared__ int   si[512];
    __shared__ float ssig[KK];
    int g = blockIdx.x, t = threadIdx.x;
    sv[t] = (t < NRr) ? dout[SC_OFF + g*NRr + t] : -3.402823466e+38f;
    si[t] = t;
    __syncthreads();
    for (int k = 2; k <= 512; k <<= 1) {
        for (int j = k >> 1; j > 0; j >>= 1) {
            int ixj = t ^ j;
            if (ixj > t) {
                float av = sv[t], bv = sv[ixj];
                int ai = si[t], bi = si[ixj];
                bool aFirst = (av > bv) || (av == bv && ai < bi);
                bool up = ((t & k) == 0);
                bool doswap = up ? (!aFirst) : aFirst;
                if (doswap) { sv[t] = bv; sv[ixj] = av; si[t] = bi; si[ixj] = ai; }
            }
            __syncthreads();
        }
    }
    for (int i = t; i < KK; i += 512) {
        float v = sv[i];
        ssig[i] = 1.f / (1.f + expf(-v));
        int li = si[i];
        dout[PERM_OFF + g*KK + i] = (float)(g*NRr + li);
        dout[BAT_OFF  + g*KK + i] = (float)g;
    }
    __syncthreads();
    for (int j = t; j < KK*OC; j += 512) {
        int i = j >> 6, c = j & 63;
        int li = si[i];
        dout[XP_OFF + (size_t)(g*KK + i)*OC + c] =
            g_out[((size_t)(g*NRr + li))*OC + c] * ssig[i];
    }
}

// ---------------- launch ---------------------------------------------------
extern "C" void kernel_launch(void* const* d_in, const int* in_sizes, int n_in,
                              void* d_out, int out_size) {
    const float* x      = (const float*)d_in[0];
    const int*   ei     = (const int*)  d_in[1];
    const float* eattr  = (const float*)d_in[2];
    // d_in[3] = batch (recomputed analytically)
    const float* basis  = (const float*)d_in[4];
    const float* roicom = (const float*)d_in[5];
    const float* ew_w   = (const float*)d_in[6];
    const float* ew_b   = (const float*)d_in[7];
    const float* cbias  = (const float*)d_in[8];
    const float* gam    = (const float*)d_in[9];
    const float* bet    = (const float*)d_in[10];
    const float* W1     = (const float*)d_in[11];
    const float* b1     = (const float*)d_in[12];
    const float* w2     = (const float*)d_in[13];
    const float* b2     = (const float*)d_in[14];
    float* dout = (float*)d_out;

    static cudaStream_t s1 = (cudaStream_t)0;
    static cudaEvent_t  e0 = (cudaEvent_t)0, e1 = (cudaEvent_t)0;
    if (!s1) {
        cudaStreamCreateWithFlags(&s1, cudaStreamNonBlocking);
        cudaEventCreateWithFlags(&e0, cudaEventDisableTiming);
        cudaEventCreateWithFlags(&e1, cudaEventDisableTiming);
    }

    // fork: side stream builds CSR + gate table while main stream does the GEMM
    cudaEventRecord(e0, 0);
    cudaStreamWaitEvent(s1, e0, 0);
    k_tab<<<QT+1, OC, 0, s1>>>(ew_w, ew_b);
    k_csr<<<NB, 256, 0, s1>>>(ei, eattr);
    cudaEventRecord(e1, s1);

    // main stream: fused roik+xt GEMM
    dim3 gx(NRr, 2);
    k_xt<<<gx, 256>>>(x, basis, roicom);

    // join, then fused gather+LN+score -> top
    cudaStreamWaitEvent(0, e1, 0);
    k_gather<<<NT/32, 256>>>(cbias, gam, bet, W1, b1, w2, b2, dout);
    k_top<<<NB, 512>>>(dout);
}

// round 10
// speedup vs baseline: 1.6528x; 1.6528x over previous
#include <cuda_runtime.h>
#include <math.h>

#define NB   256            // graphs
#define NRr  268            // ROIs per graph
#define NT   (NB*NRr)       // total nodes = 68608
#define IC   256
#define OC   64
#define NCm  7
#define DEG  32
#define EPG  (NRr*DEG)      // edges per graph = 8576
#define ET   (NT*DEG)       // total edges = 2195456
#define KK   214            // top-k per graph
#define QT   256            // sigmoid table resolution
#define LN_EPS 1e-5f
#define CHUNK (EPG/8)       // 1072 edges per warp in k_csr

// k_xt smem layout
#define XS_STRIDE 68        // 256 rows (graphs) x 64 k, padded
#define WS_STRIDE 72        // 64 rows (k) x 64 out, halves at col 0 and 36
#define XS_FLOATS (256*XS_STRIDE)
#define WS_FLOATS (64*WS_STRIDE)

// output layout (float32, concatenated in reference return order)
#define XP_OFF   0
#define BAT_OFF  (NB*KK*OC)                 // 3506176
#define SC_OFF   (BAT_OFF + NB*KK)          // 3560960
#define PERM_OFF (SC_OFF + NT)              // 3629568

// ---------------- scratch (device globals; no allocation allowed) ----------
__device__ float g_tab[(QT+1)*OC];          // sigmoid(ea*w[c]+b[c]) table, row QT = self-loop gate
__device__ float g_xt[NT*OC];               // xt (per-node transform result)
__device__ float g_out[NT*OC];              // h after fused conv+ELU+LN
__device__ int   g_bsrc[ET];                // CSR bucket: global src node per slot
__device__ float g_bea[ET];                 // CSR bucket: edge_attr per slot
__device__ int   g_off[NT+1];               // CSR offsets (global edge space)

// ---------------- kernels --------------------------------------------------
__global__ void k_tab(const float* __restrict__ w, const float* __restrict__ b) {
    int q = blockIdx.x, c = threadIdx.x;
    double x = ((double)q / (double)QT) * (double)w[c] + (double)b[c];
    g_tab[q*OC + c] = (float)(1.0 / (1.0 + exp(-x)));
}

// Fused ROI-kernel mix + grouped GEMM, smem-staged.
// Block = ROI r. Per k-tile: X(256 graphs x 64k) and mixed W(64k x 64o) staged
// in smem; thread = 2 graphs x 32 outputs; per k: 8 conflict-free LDS.128 (W)
// + 64 FFMA (7.5:1). All gmem loads coalesced.
__global__ void __launch_bounds__(256, 2) k_xt(const float* __restrict__ x,
                                               const float* __restrict__ basis,
                                               const float* __restrict__ rc) {
    extern __shared__ float sm[];           // [XS_FLOATS] X | [WS_FLOATS] W
    float* Xs = sm;
    float* Ws = sm + XS_FLOATS;
    __shared__ float cws[NCm];
    int r = blockIdx.x;
    int tid = threadIdx.x;
    int w = tid >> 5, lane = tid & 31;
    int gp = tid >> 1;                      // 0..127
    int oh = tid & 1;                       // output half
    int g0 = gp, g1 = gp + 128;
    int woff = oh ? 36 : 0;

    if (tid == 0) {
        double v[NCm]; double m = -1e300;
        #pragma unroll
        for (int c = 0; c < NCm; c++) { v[c] = (double)rc[r*NCm + c]; if (v[c] > m) m = v[c]; }
        double s = 0.0;
        #pragma unroll
        for (int c = 0; c < NCm; c++) { v[c] = exp(v[c] - m); s += v[c]; }
        #pragma unroll
        for (int c = 0; c < NCm; c++) cws[c] = (float)(v[c] / s);
    }
    __syncthreads();
    float cwv[NCm];
    #pragma unroll
    for (int c = 0; c < NCm; c++) cwv[c] = cws[c];

    float4 a0[8], a1[8];
    #pragma unroll
    for (int j = 0; j < 8; j++) {
        a0[j] = make_float4(0.f,0.f,0.f,0.f);
        a1[j] = make_float4(0.f,0.f,0.f,0.f);
    }
    const float4* b4 = (const float4*)basis;

    for (int kt = 0; kt < 4; kt++) {
        __syncthreads();
        // stage mixed W k-tile (split-half layout)
        for (int i = tid; i < 64*16; i += 256) {
            int kk = i >> 4, c4 = i & 15;   // c4*4 = output col
            float4 acc = make_float4(0.f,0.f,0.f,0.f);
            #pragma unroll
            for (int c = 0; c < NCm; c++) {
                float4 t = b4[c*(IC*OC/4) + (kt*64 + kk)*(OC/4) + c4];
                acc.x += cwv[c]*t.x; acc.y += cwv[c]*t.y;
                acc.z += cwv[c]*t.z; acc.w += cwv[c]*t.w;
            }
            int col = c4*4;
            int off = (col < 32) ? col : (36 + col - 32);
            *(float4*)(Ws + kk*WS_STRIDE + off) = acc;
        }
        // stage X tile: warp reads 256B of one graph-row per instruction
        for (int g = w; g < 256; g += 8) {
            float2 v = ((const float2*)(x + ((size_t)(g*NRr + r))*IC + kt*64))[lane];
            ((float2*)(Xs + g*XS_STRIDE))[lane] = v;
        }
        __syncthreads();
        // compute
        for (int k4 = 0; k4 < 16; k4++) {
            float4 xa = *(const float4*)(Xs + g0*XS_STRIDE + k4*4);
            float4 xb = *(const float4*)(Xs + g1*XS_STRIDE + k4*4);
            #pragma unroll
            for (int kk = 0; kk < 4; kk++) {
                const float4* wr = (const float4*)(Ws + (k4*4 + kk)*WS_STRIDE + woff);
                float fa = (&xa.x)[kk], fb = (&xb.x)[kk];
                #pragma unroll
                for (int j = 0; j < 8; j++) {
                    float4 wv = wr[j];
                    a0[j].x += fa*wv.x; a0[j].y += fa*wv.y; a0[j].z += fa*wv.z; a0[j].w += fa*wv.w;
                    a1[j].x += fb*wv.x; a1[j].y += fb*wv.y; a1[j].z += fb*wv.z; a1[j].w += fb*wv.w;
                }
            }
        }
    }
    float4* o0 = (float4*)(g_xt + ((size_t)(g0*NRr + r))*OC + oh*32);
    float4* o1 = (float4*)(g_xt + ((size_t)(g1*NRr + r))*OC + oh*32);
    #pragma unroll
    for (int j = 0; j < 8; j++) { o0[j] = a0[j]; o1[j] = a1[j]; }
}

// Deterministic per-graph CSR build, counting-sort style, all 8 warps active.
// Bucket order = ascending edge id (stable), matching XLA scatter order.
__global__ void __launch_bounds__(256) k_csr(const int* __restrict__ ei,
                                             const float* __restrict__ eattr) {
    __shared__ unsigned short ldst[EPG];    // local dst per edge (17 KB)
    __shared__ unsigned short lpos[EPG];    // bucket slot per edge (17 KB)
    __shared__ int cw[8][NRr];              // per-warp histogram -> per-warp base (8.6 KB)
    __shared__ int tot[NRr], off[NRr];
    int g = blockIdx.x, tid = threadIdx.x;
    int lane = tid & 31, wid = tid >> 5;
    int base = g*EPG;
    int cbeg = wid*CHUNK;

    for (int i = tid; i < EPG; i += 256)
        ldst[i] = (unsigned short)(ei[ET + base + i] - g*NRr);
    for (int i = tid; i < 8*NRr; i += 256) ((int*)cw)[i] = 0;
    __syncthreads();

    for (int i = cbeg + lane; i < cbeg + CHUNK; i += 32)
        atomicAdd(&cw[wid][ldst[i]], 1);
    __syncthreads();

    for (int d = tid; d < NRr; d += 256) {
        int s = 0;
        #pragma unroll
        for (int w = 0; w < 8; w++) s += cw[w][d];
        tot[d] = s;
    }
    __syncthreads();

    if (wid == 0) {
        int carry = 0;
        for (int c = 0; c < 9; c++) {
            int idx = c*32 + lane;
            int v = (idx < NRr) ? tot[idx] : 0;
            int incl = v;
            #pragma unroll
            for (int o = 1; o < 32; o <<= 1) {
                int t = __shfl_up_sync(0xffffffffu, incl, o);
                if (lane >= o) incl += t;
            }
            if (idx < NRr) off[idx] = incl - v + carry;
            carry += __shfl_sync(0xffffffffu, incl, 31);
        }
    }
    __syncthreads();

    for (int d = tid; d < NRr; d += 256) {
        int run = off[d];
        #pragma unroll
        for (int w = 0; w < 8; w++) { int t = cw[w][d]; cw[w][d] = run; run += t; }
        g_off[g*NRr + d] = base + off[d];
    }
    if (g == NB-1 && tid == 0) g_off[NT] = ET;
    __syncthreads();

    for (int it = 0; it < (CHUNK + 31)/32; it++) {
        int idx = cbeg + it*32 + lane;
        bool valid = (idx < cbeg + CHUNK);
        int d = valid ? (int)ldst[idx] : (NRr + lane);
        unsigned mask = __match_any_sync(0xffffffffu, d);
        int rank = __popc(mask & ((1u << lane) - 1u));
        int leader = __ffs(mask) - 1;
        int prior = valid ? cw[wid][d] : 0;
        if (valid && lane == leader) cw[wid][d] = prior + __popc(mask);
        if (valid) lpos[idx] = (unsigned short)(prior + rank);
    }
    __syncthreads();

    for (int i = tid; i < EPG; i += 256) {
        int pos = base + (int)lpos[i];
        g_bsrc[pos] = ei[base + i];
        g_bea[pos]  = eattr[base + i];
    }
}

// Fused gather + self-loop + bias + ELU + LayerNorm. Warp per dst node.
// Deterministic: fixed (edge-id ascending) summation order, self-loop last.
__global__ void __launch_bounds__(256) k_gather(const float* __restrict__ cbias,
                                                const float* __restrict__ gam,
                                                const float* __restrict__ bet) {
    __shared__ int   s_s[8][128];
    __shared__ float s_e[8][128];
    int w = threadIdx.x >> 5, lane = threadIdx.x & 31;
    int n = blockIdx.x*8 + w;
    int o0 = g_off[n];
    int cnt = g_off[n+1] - o0;
    if (cnt > 128) cnt = 128;               // statistically impossible (mean 32)
    for (int j = lane; j < cnt; j += 32) {
        s_s[w][j] = g_bsrc[o0 + j];
        s_e[w][j] = g_bea [o0 + j];
    }
    __syncwarp();
    float2 acc = make_float2(0.f, 0.f);
    #pragma unroll 4
    for (int j = 0; j < cnt; j++) {
        int s = s_s[w][j];
        float ea = s_e[w][j];
        float f = ea * (float)QT;
        int q = (int)f; if (q > QT-1) q = QT-1;
        float fr = f - (float)q;
        float2 t0 = ((const float2*)(g_tab + q*OC))[lane];
        float2 t1 = ((const float2*)(g_tab + q*OC + OC))[lane];
        float2 xv = ((const float2*)(g_xt + (size_t)s*OC))[lane];
        acc.x += xv.x * (t0.x + (t1.x - t0.x)*fr);
        acc.y += xv.y * (t0.y + (t1.y - t0.y)*fr);
    }
    // self-loop (appended last in reference), then bias
    float2 sg = ((const float2*)(g_tab + QT*OC))[lane];
    float2 xn = ((const float2*)(g_xt + (size_t)n*OC))[lane];
    acc.x += xn.x * sg.x; acc.y += xn.y * sg.y;
    float2 bb = ((const float2*)cbias)[lane];
    acc.x += bb.x; acc.y += bb.y;
    // ELU
    acc.x = acc.x > 0.f ? acc.x : expm1f(acc.x);
    acc.y = acc.y > 0.f ? acc.y : expm1f(acc.y);
    // LayerNorm (warp reduce over 64 channels)
    float s1 = acc.x + acc.y;
    #pragma unroll
    for (int o = 16; o; o >>= 1) s1 += __shfl_xor_sync(0xffffffffu, s1, o);
    float mu = s1 * (1.f/64.f);
    float dx = acc.x - mu, dy = acc.y - mu;
    float s2 = dx*dx + dy*dy;
    #pragma unroll
    for (int o = 16; o; o >>= 1) s2 += __shfl_xor_sync(0xffffffffu, s2, o);
    float inv = 1.0f / sqrtf(s2*(1.f/64.f) + LN_EPS);
    float2 gm = ((const float2*)gam)[lane];
    float2 bt = ((const float2*)bet)[lane];
    float2 h;
    h.x = dx*inv*gm.x + bt.x;
    h.y = dy*inv*gm.y + bt.y;
    ((float2*)(g_out + (size_t)n*OC))[lane] = h;
}

// attention scores: score[n] = tanh(h@W1+b1)@w2 + b2 ; written straight into d_out
__global__ void __launch_bounds__(256) k_score(const float* __restrict__ W1,
                                               const float* __restrict__ b1,
                                               const float* __restrict__ w2,
                                               const float* __restrict__ b2,
                                               float* __restrict__ dout) {
    __shared__ float W1s[OC*OC];
    __shared__ float b1s[OC];
    __shared__ float w2s[OC];
    for (int i = threadIdx.x; i < OC*OC; i += 256) W1s[i] = W1[i];
    if (threadIdx.x < OC) { b1s[threadIdx.x] = b1[threadIdx.x]; w2s[threadIdx.x] = w2[threadIdx.x]; }
    __syncthreads();
    int n = blockIdx.x*256 + threadIdx.x;
    if (n >= NT) return;
    float h[64];
    const float4* hr = (const float4*)(g_out + (size_t)n*OC);
    #pragma unroll
    for (int i = 0; i < 16; i++) {
        float4 t = hr[i];
        h[i*4+0]=t.x; h[i*4+1]=t.y; h[i*4+2]=t.z; h[i*4+3]=t.w;
    }
    float sc = b2[0];
    for (int o4 = 0; o4 < 16; o4++) {
        float4 u = ((const float4*)b1s)[o4];
        #pragma unroll 8
        for (int c = 0; c < 64; c++) {
            float hv = h[c];
            float4 w = ((const float4*)W1s)[c*16 + o4];
            u.x += hv*w.x; u.y += hv*w.y; u.z += hv*w.z; u.w += hv*w.w;
        }
        float4 w2v = ((const float4*)w2s)[o4];
        sc += tanhf(u.x)*w2v.x + tanhf(u.y)*w2v.y + tanhf(u.z)*w2v.z + tanhf(u.w)*w2v.w;
    }
    dout[SC_OFF + n] = sc;
}

// per-graph top-K via full bitonic sort (desc value, tie: asc index like jax top_k)
__global__ void __launch_bounds__(512) k_top(float* __restrict__ dout) {
    __shared__ float sv[512];
    __shared__ int   si[512];
    __shared__ float ssig[KK];
    int g = blockIdx.x, t = threadIdx.x;
    sv[t] = (t < NRr) ? dout[SC_OFF + g*NRr + t] : -3.402823466e+38f;
    si[t] = t;
    __syncthreads();
    for (int k = 2; k <= 512; k <<= 1) {
        for (int j = k >> 1; j > 0; j >>= 1) {
            int ixj = t ^ j;
            if (ixj > t) {
                float av = sv[t], bv = sv[ixj];
                int ai = si[t], bi = si[ixj];
                bool aFirst = (av > bv) || (av == bv && ai < bi);
                bool up = ((t & k) == 0);
                bool doswap = up ? (!aFirst) : aFirst;
                if (doswap) { sv[t] = bv; sv[ixj] = av; si[t] = bi; si[ixj] = ai; }
            }
            __syncthreads();
        }
    }
    for (int i = t; i < KK; i += 512) {
        float v = sv[i];
        ssig[i] = 1.f / (1.f + expf(-v));
        int li = si[i];
        dout[PERM_OFF + g*KK + i] = (float)(g*NRr + li);
        dout[BAT_OFF  + g*KK + i] = (float)g;
    }
    __syncthreads();
    for (int j = t; j < KK*OC; j += 512) {
        int i = j >> 6, c = j & 63;
        int li = si[i];
        dout[XP_OFF + (size_t)(g*KK + i)*OC + c] =
            g_out[((size_t)(g*NRr + li))*OC + c] * ssig[i];
    }
}

// ---------------- launch ---------------------------------------------------
extern "C" void kernel_launch(void* const* d_in, const int* in_sizes, int n_in,
                              void* d_out, int out_size) {
    const float* x      = (const float*)d_in[0];
    const int*   ei     = (const int*)  d_in[1];
    const float* eattr  = (const float*)d_in[2];
    // d_in[3] = batch (recomputed analytically)
    const float* basis  = (const float*)d_in[4];
    const float* roicom = (const float*)d_in[5];
    const float* ew_w   = (const float*)d_in[6];
    const float* ew_b   = (const float*)d_in[7];
    const float* cbias  = (const float*)d_in[8];
    const float* gam    = (const float*)d_in[9];
    const float* bet    = (const float*)d_in[10];
    const float* W1     = (const float*)d_in[11];
    const float* b1     = (const float*)d_in[12];
    const float* w2     = (const float*)d_in[13];
    const float* b2     = (const float*)d_in[14];
    float* dout = (float*)d_out;

    static cudaStream_t s1 = (cudaStream_t)0;
    static cudaEvent_t  e0 = (cudaEvent_t)0, e1 = (cudaEvent_t)0;
    if (!s1) {
        cudaStreamCreateWithFlags(&s1, cudaStreamNonBlocking);
        cudaEventCreateWithFlags(&e0, cudaEventDisableTiming);
        cudaEventCreateWithFlags(&e1, cudaEventDisableTiming);
        cudaFuncSetAttribute(k_xt, cudaFuncAttributeMaxDynamicSharedMemorySize,
                             (XS_FLOATS + WS_FLOATS)*(int)sizeof(float));
    }

    // fork: side stream builds CSR + gate table while main stream does the GEMM
    cudaEventRecord(e0, 0);
    cudaStreamWaitEvent(s1, e0, 0);
    k_tab<<<QT+1, OC, 0, s1>>>(ew_w, ew_b);
    k_csr<<<NB, 256, 0, s1>>>(ei, eattr);
    cudaEventRecord(e1, s1);

    // main stream: fused mix+GEMM
    k_xt<<<NRr, 256, (XS_FLOATS + WS_FLOATS)*sizeof(float)>>>(x, basis, roicom);

    // join, then gather+LN -> score -> top
    cudaStreamWaitEvent(0, e1, 0);
    k_gather<<<NT/8, 256>>>(cbias, gam, bet);
    k_score<<<(NT + 255)/256, 256>>>(W1, b1, w2, b2, dout);
    k_top<<<NB, 512>>>(dout);
}